// round 2
// baseline (speedup 1.0000x reference)
#include <cuda_runtime.h>

// PatchChamferDistance: B=32, G=64, P=256, D=3 (fp32)
// d2[i][j] = max(|p_i|^2 + |q_j|^2 - 2 p_i.q_j, 0)
// out = mean_patch( mean_i min_j d2 + mean_j min_i d2 )
//
// R2 design: 64 threads/CTA, each thread owns 4 pred rows + 4 tgt rows packed
// as f32x2 pairs. Scan operand stored in smem pre-scaled/duplicated:
//   A[j] = { -2x, -2x, -2y, -2y },  B[j] = { -2z, -2z, w, w }
// so each 2-row eval is 3x fma.rn.f32x2 + 1x add.rn.f32x2, no packing in loop.

#define BGQ  2048
#define NP   256
#define T    64
#define INF  3.402823e38f

__device__ __forceinline__ unsigned long long pk2(float a, float b) {
    unsigned long long r;
    asm("mov.b64 %0, {%1, %2};" : "=l"(r) : "f"(a), "f"(b));
    return r;
}
__device__ __forceinline__ unsigned long long fma2(unsigned long long a,
                                                   unsigned long long b,
                                                   unsigned long long c) {
    unsigned long long d;
    asm("fma.rn.f32x2 %0, %1, %2, %3;" : "=l"(d) : "l"(a), "l"(b), "l"(c));
    return d;
}
__device__ __forceinline__ unsigned long long add2(unsigned long long a,
                                                   unsigned long long b) {
    unsigned long long d;
    asm("add.rn.f32x2 %0, %1, %2;" : "=l"(d) : "l"(a), "l"(b));
    return d;
}
__device__ __forceinline__ void upk2(unsigned long long v, float& lo, float& hi) {
    asm("mov.b64 {%0, %1}, %2;" : "=f"(lo), "=f"(hi) : "l"(v));
}

__global__ void pcd_zero_kernel(float* out) { out[0] = 0.0f; }

__global__ __launch_bounds__(T, 12)
void pcd_chamfer_kernel(const float* __restrict__ pred,
                        const float* __restrict__ tgt,
                        float* __restrict__ out)
{
    // duplicated/pre-scaled scan operands: 16B per point per half
    __shared__ ulonglong2 sqA[NP], sqB[NP];   // targets
    __shared__ ulonglong2 spA[NP], spB[NP];   // preds
    __shared__ float wsum[2];

    const int patch = blockIdx.x;
    const int t     = threadIdx.x;

    const float* pb = pred + (size_t)patch * NP * 3;
    const float* qb = tgt  + (size_t)patch * NP * 3;

    // raw coords of owned rows (4 per cloud), rows j = t + 64*r
    float prx[4], pry[4], prz[4], prw[4];
    float trx[4], tryy[4], trz[4], trw[4];

#pragma unroll
    for (int r = 0; r < 4; r++) {
        int j = t + T * r;
        float x = pb[j * 3 + 0], y = pb[j * 3 + 1], z = pb[j * 3 + 2];
        float w = x * x + y * y + z * z;
        prx[r] = x; pry[r] = y; prz[r] = z; prw[r] = w;
        spA[j] = make_ulonglong2(pk2(-2.f * x, -2.f * x), pk2(-2.f * y, -2.f * y));
        spB[j] = make_ulonglong2(pk2(-2.f * z, -2.f * z), pk2(w, w));

        x = qb[j * 3 + 0]; y = qb[j * 3 + 1]; z = qb[j * 3 + 2];
        w = x * x + y * y + z * z;
        trx[r] = x; tryy[r] = y; trz[r] = z; trw[r] = w;
        sqA[j] = make_ulonglong2(pk2(-2.f * x, -2.f * x), pk2(-2.f * y, -2.f * y));
        sqB[j] = make_ulonglong2(pk2(-2.f * z, -2.f * z), pk2(w, w));
    }
    __syncthreads();

    // pack owned rows into f32x2 pairs: pair0 = rows (0,1), pair1 = rows (2,3)
    unsigned long long px[2], py[2], pz[2], pw[2];
    unsigned long long qx[2], qy[2], qz[2], qw[2];
#pragma unroll
    for (int h = 0; h < 2; h++) {
        px[h] = pk2(prx[2 * h], prx[2 * h + 1]);
        py[h] = pk2(pry[2 * h], pry[2 * h + 1]);
        pz[h] = pk2(prz[2 * h], prz[2 * h + 1]);
        pw[h] = pk2(prw[2 * h], prw[2 * h + 1]);
        qx[h] = pk2(trx[2 * h], trx[2 * h + 1]);
        qy[h] = pk2(tryy[2 * h], tryy[2 * h + 1]);
        qz[h] = pk2(trz[2 * h], trz[2 * h + 1]);
        qw[h] = pk2(trw[2 * h], trw[2 * h + 1]);
    }

    float fmn[4] = {INF, INF, INF, INF};   // forward mins (pred rows)
    float bmn[4] = {INF, INF, INF, INF};   // backward mins (tgt rows)

#pragma unroll 8
    for (int j = 0; j < NP; j++) {
        // ---- forward: owned pred rows vs target j ----
        {
            ulonglong2 a = sqA[j];   // {-2qx,-2qx, -2qy,-2qy}
            ulonglong2 b = sqB[j];   // {-2qz,-2qz,  qw, qw }
#pragma unroll
            for (int h = 0; h < 2; h++) {
                unsigned long long acc = fma2(px[h], a.x, pw[h]);
                acc = fma2(py[h], a.y, acc);
                acc = fma2(pz[h], b.x, acc);
                acc = add2(acc, b.y);
                float d0, d1; upk2(acc, d0, d1);
                fmn[2 * h]     = fminf(fmn[2 * h], d0);
                fmn[2 * h + 1] = fminf(fmn[2 * h + 1], d1);
            }
        }
        // ---- backward: owned tgt rows vs pred j ----
        {
            ulonglong2 a = spA[j];
            ulonglong2 b = spB[j];
#pragma unroll
            for (int h = 0; h < 2; h++) {
                unsigned long long acc = fma2(qx[h], a.x, qw[h]);
                acc = fma2(qy[h], a.y, acc);
                acc = fma2(qz[h], b.x, acc);
                acc = add2(acc, b.y);
                float d0, d1; upk2(acc, d0, d1);
                bmn[2 * h]     = fminf(bmn[2 * h], d0);
                bmn[2 * h + 1] = fminf(bmn[2 * h + 1], d1);
            }
        }
    }

    // clamp commutes with min; sum this thread's 8 row contributions
    float v = 0.f;
#pragma unroll
    for (int r = 0; r < 4; r++)
        v += fmaxf(fmn[r], 0.f) + fmaxf(bmn[r], 0.f);

    // block reduction: 2 warps
#pragma unroll
    for (int o = 16; o > 0; o >>= 1)
        v += __shfl_down_sync(0xffffffffu, v, o);
    if ((t & 31) == 0) wsum[t >> 5] = v;
    __syncthreads();
    if (t == 0) {
        float s = wsum[0] + wsum[1];
        atomicAdd(out, s * (1.0f / ((float)NP * (float)BGQ)));
    }
}

extern "C" void kernel_launch(void* const* d_in, const int* in_sizes, int n_in,
                              void* d_out, int out_size)
{
    const float* pred = (const float*)d_in[0];
    const float* tgt  = (const float*)d_in[1];
    float* out = (float*)d_out;

    pcd_zero_kernel<<<1, 1>>>(out);
    pcd_chamfer_kernel<<<BGQ, T>>>(pred, tgt, out);
}

// round 3
// speedup vs baseline: 1.6208x; 1.6208x over previous
#include <cuda_runtime.h>

// PatchChamferDistance: B=32, G=64, P=256, D=3 (fp32)
// d2[i][j] = max(|p_i|^2 + |q_j|^2 - 2 p_i.q_j, 0)
// out = mean_patch( mean_i min_j d2 + mean_j min_i d2 )
//
// R3: 128 thr/CTA, scalar FFMA, 2 pred + 2 tgt rows per thread.
// Scan operand prescaled in smem as {-2x,-2y,-2z,w} so each eval is
// 3 FFMA + 1 FADD + 1 FMNMX:  d = ((pw + px*ax) + py*ay + pz*az) + aw.

#define BGQ  2048
#define NP   256
#define T    128
#define INF  3.402823e38f

__global__ void pcd_zero_kernel(float* out) { out[0] = 0.0f; }

__global__ __launch_bounds__(T)
void pcd_chamfer_kernel(const float* __restrict__ pred,
                        const float* __restrict__ tgt,
                        float* __restrict__ out)
{
    __shared__ float4 sp[NP];   // pred, prescaled {-2x,-2y,-2z,w}
    __shared__ float4 sq[NP];   // tgt,  prescaled {-2x,-2y,-2z,w}
    __shared__ float wsum[T / 32];

    const int patch = blockIdx.x;
    const int t     = threadIdx.x;

    const float* pb = pred + (size_t)patch * NP * 3;
    const float* qb = tgt  + (size_t)patch * NP * 3;

    // owned rows (raw coords + norm), rows t and t+128
    float px[2], py[2], pz[2], pw[2];
    float qx[2], qy[2], qz[2], qw[2];

#pragma unroll
    for (int r = 0; r < 2; r++) {
        int j = t + T * r;
        float x = pb[j * 3 + 0], y = pb[j * 3 + 1], z = pb[j * 3 + 2];
        float w = x * x + y * y + z * z;
        px[r] = x; py[r] = y; pz[r] = z; pw[r] = w;
        sp[j] = make_float4(-2.f * x, -2.f * y, -2.f * z, w);

        x = qb[j * 3 + 0]; y = qb[j * 3 + 1]; z = qb[j * 3 + 2];
        w = x * x + y * y + z * z;
        qx[r] = x; qy[r] = y; qz[r] = z; qw[r] = w;
        sq[j] = make_float4(-2.f * x, -2.f * y, -2.f * z, w);
    }
    __syncthreads();

    float fmn[2] = {INF, INF};   // forward mins (owned pred rows)
    float bmn[2] = {INF, INF};   // backward mins (owned tgt rows)

#pragma unroll 8
    for (int j = 0; j < NP; j++) {
        float4 a = sq[j];        // warp-uniform -> LDS broadcast
#pragma unroll
        for (int r = 0; r < 2; r++) {
            float d = fmaf(px[r], a.x, pw[r]);
            d = fmaf(py[r], a.y, d);
            d = fmaf(pz[r], a.z, d);
            d += a.w;
            fmn[r] = fminf(fmn[r], d);
        }
        float4 b = sp[j];
#pragma unroll
        for (int r = 0; r < 2; r++) {
            float d = fmaf(qx[r], b.x, qw[r]);
            d = fmaf(qy[r], b.y, d);
            d = fmaf(qz[r], b.z, d);
            d += b.w;
            bmn[r] = fminf(bmn[r], d);
        }
    }

    // clamp commutes with min; sum this thread's 4 row contributions
    float v = fmaxf(fmn[0], 0.f) + fmaxf(fmn[1], 0.f)
            + fmaxf(bmn[0], 0.f) + fmaxf(bmn[1], 0.f);

    // block reduction: 4 warps
#pragma unroll
    for (int o = 16; o > 0; o >>= 1)
        v += __shfl_down_sync(0xffffffffu, v, o);
    if ((t & 31) == 0) wsum[t >> 5] = v;
    __syncthreads();
    if (t == 0) {
        float s = wsum[0] + wsum[1] + wsum[2] + wsum[3];
        atomicAdd(out, s * (1.0f / ((float)NP * (float)BGQ)));
    }
}

extern "C" void kernel_launch(void* const* d_in, const int* in_sizes, int n_in,
                              void* d_out, int out_size)
{
    const float* pred = (const float*)d_in[0];
    const float* tgt  = (const float*)d_in[1];
    float* out = (float*)d_out;

    pcd_zero_kernel<<<1, 1>>>(out);
    pcd_chamfer_kernel<<<BGQ, T>>>(pred, tgt, out);
}